// round 3
// baseline (speedup 1.0000x reference)
#include <cuda_runtime.h>
#include <cuda_bf16.h>
#include <math.h>

// Problem constants (fixed by setup_inputs)
#define Bq   32
#define Sq   128
#define Cq   384
#define Hh   8
#define Ww   512
#define Nkv  (Hh*Ww)        // 4096
#define HD2  192            // head dim for nh=2 cross-attn
// SIGMA = 3 -> 2*sigma^2 = 18

// ---------------------------------------------------------------------------
// Scratch (single __device__ global; no allocations allowed)
// ---------------------------------------------------------------------------
#define SZ_BWC   (Bq*Ww*Cq)          // 6291456
#define SZ_BW2C  (Bq*Ww*2*Cq)        // 12582912
#define SZ_BSC   (Bq*Sq*Cq)          // 1572864
#define SZ_BS2C  (Bq*Sq*2*Cq)        // 3145728
#define SZ_SC1   (Bq*2*Sq*Sq)        // 1048576
#define SZ_SC2   (Bq*2*Sq*Ww)        // 4194304
#define SZ_SCM   (Bq*Sq*Ww)          // 2097152
#define SZ_PT    (Bq*Sq)             // 4096

#define OFF_DECM   0
#define OFF_DEC    (OFF_DECM + SZ_BWC)
#define OFF_LNDEC  (OFF_DEC + SZ_BWC)
#define OFF_KVMAIN (OFF_LNDEC + SZ_BWC)
#define OFF_KV2    (OFF_KVMAIN + SZ_BW2C)
#define OFF_KV1    (OFF_KV2 + SZ_BW2C)
#define OFF_QH     (OFF_KV1 + SZ_BS2C)
#define OFF_P0     (OFF_QH   + SZ_BSC)
#define OFF_LNA    (OFF_P0   + SZ_BSC)
#define OFF_LNB    (OFF_LNA  + SZ_BSC)
#define OFF_QH1    (OFF_LNB  + SZ_BSC)
#define OFF_X1     (OFF_QH1  + SZ_BSC)
#define OFF_P1     (OFF_X1   + SZ_BSC)
#define OFF_QH2    (OFF_P1   + SZ_BSC)
#define OFF_X2     (OFF_QH2  + SZ_BSC)
#define OFF_P2     (OFF_X2   + SZ_BSC)
#define OFF_TBUF   (OFF_P2   + SZ_BSC)
#define OFF_XMAIN  (OFF_TBUF + SZ_BSC)
#define OFF_SC1    (OFF_XMAIN+ SZ_BSC)
#define OFF_SC2    (OFF_SC1  + SZ_SC1)
#define OFF_SCM    (OFF_SC2  + SZ_SC2)
#define OFF_PT     (OFF_SCM  + SZ_SCM)
#define SCR_TOTAL  (OFF_PT + SZ_PT)

__device__ float SCR[SCR_TOTAL];

// ---------------------------------------------------------------------------
// Block reductions
// ---------------------------------------------------------------------------
__device__ __forceinline__ float blk_reduce_sum(float v) {
    __shared__ float sh[32];
    int lane = threadIdx.x & 31, w = threadIdx.x >> 5;
    #pragma unroll
    for (int o = 16; o; o >>= 1) v += __shfl_xor_sync(0xffffffffu, v, o);
    __syncthreads();
    if (lane == 0) sh[w] = v;
    __syncthreads();
    int nw = (blockDim.x + 31) >> 5;
    float r = (lane < nw) ? sh[lane] : 0.f;
    #pragma unroll
    for (int o = 16; o; o >>= 1) r += __shfl_xor_sync(0xffffffffu, r, o);
    return r;
}

__device__ __forceinline__ float blk_reduce_max(float v) {
    __shared__ float sh[32];
    int lane = threadIdx.x & 31, w = threadIdx.x >> 5;
    #pragma unroll
    for (int o = 16; o; o >>= 1) v = fmaxf(v, __shfl_xor_sync(0xffffffffu, v, o));
    __syncthreads();
    if (lane == 0) sh[w] = v;
    __syncthreads();
    int nw = (blockDim.x + 31) >> 5;
    float r = (lane < nw) ? sh[lane] : -3.4e38f;
    #pragma unroll
    for (int o = 16; o; o >>= 1) r = fmaxf(r, __shfl_xor_sync(0xffffffffu, r, o));
    return r;
}

// ---------------------------------------------------------------------------
// Generic strided-batched SGEMM: C = alpha * A @ op(B) (+ bias)
// A: M x K row-major (lda); B: K x N (ldb) or, if transB, N x K (ldb)
// Batch index z decomposes into (outer, inner): ptr += o*s?o + i*s?i
// REQUIREMENTS (met by all call sites): M % 64 == 0, N % 64 == 0, K % 16 == 0,
// all leading dims multiples of 4 (float4 loads).
// ---------------------------------------------------------------------------
__global__ void sgemm_kernel(const float* __restrict__ A, const float* __restrict__ B,
                             const float* __restrict__ bias, float* __restrict__ C,
                             int M, int N, int K, int lda, int ldb, int ldc,
                             long long sAo, long long sAi,
                             long long sBo, long long sBi,
                             long long sCo, long long sCi,
                             int inner, float alpha, int transB)
{
    __shared__ float As[16][65];
    __shared__ float Bs[16][65];
    int z = blockIdx.z;
    int o = z / inner, ii = z - o * inner;
    A += (long long)o * sAo + (long long)ii * sAi;
    B += (long long)o * sBo + (long long)ii * sBi;
    C += (long long)o * sCo + (long long)ii * sCi;

    int tid = threadIdx.x;
    int tx = tid & 15, ty = tid >> 4;
    int row0 = blockIdx.y * 64;
    int col0 = blockIdx.x * 64;

    float acc[4][4] = {};

    for (int kk = 0; kk < K; kk += 16) {
        {   // A tile: As[k][m]
            int m  = tid >> 2;
            int k4 = (tid & 3) << 2;
            float4 av = *reinterpret_cast<const float4*>(
                &A[(long long)(row0 + m) * lda + kk + k4]);
            As[k4+0][m] = av.x; As[k4+1][m] = av.y;
            As[k4+2][m] = av.z; As[k4+3][m] = av.w;
        }
        if (!transB) {  // B is K x N
            int k  = tid >> 4;
            int n4 = (tid & 15) << 2;
            float4 bv = *reinterpret_cast<const float4*>(
                &B[(long long)(kk + k) * ldb + col0 + n4]);
            Bs[k][n4+0] = bv.x; Bs[k][n4+1] = bv.y;
            Bs[k][n4+2] = bv.z; Bs[k][n4+3] = bv.w;
        } else {        // B is N x K (C = A @ B^T)
            int n  = tid >> 2;
            int k4 = (tid & 3) << 2;
            float4 bv = *reinterpret_cast<const float4*>(
                &B[(long long)(col0 + n) * ldb + kk + k4]);
            Bs[k4+0][n] = bv.x; Bs[k4+1][n] = bv.y;
            Bs[k4+2][n] = bv.z; Bs[k4+3][n] = bv.w;
        }
        __syncthreads();
        #pragma unroll
        for (int k = 0; k < 16; k++) {
            float a0 = As[k][ty*4+0], a1 = As[k][ty*4+1];
            float a2 = As[k][ty*4+2], a3 = As[k][ty*4+3];
            float b0 = Bs[k][tx*4+0], b1 = Bs[k][tx*4+1];
            float b2 = Bs[k][tx*4+2], b3 = Bs[k][tx*4+3];
            acc[0][0] += a0*b0; acc[0][1] += a0*b1; acc[0][2] += a0*b2; acc[0][3] += a0*b3;
            acc[1][0] += a1*b0; acc[1][1] += a1*b1; acc[1][2] += a1*b2; acc[1][3] += a1*b3;
            acc[2][0] += a2*b0; acc[2][1] += a2*b1; acc[2][2] += a2*b2; acc[2][3] += a2*b3;
            acc[3][0] += a3*b0; acc[3][1] += a3*b1; acc[3][2] += a3*b2; acc[3][3] += a3*b3;
        }
        __syncthreads();
    }

    #pragma unroll
    for (int jm = 0; jm < 4; jm++) {
        int r = row0 + ty*4 + jm;
        #pragma unroll
        for (int jn = 0; jn < 4; jn++) {
            int c = col0 + tx*4 + jn;
            float v = alpha * acc[jm][jn];
            if (bias) v += bias[c];
            C[(long long)r * ldc + c] = v;
        }
    }
}

// ---------------------------------------------------------------------------
// dec mean over H:  decm[b,w,c] = mean_h kv[b, h*W + w, c]
// ---------------------------------------------------------------------------
__global__ void mean_h_kernel(const float* __restrict__ kv, float* __restrict__ out)
{
    int bw = blockIdx.x;
    int b = bw >> 9;          // /512
    int w = bw & 511;
    int c = threadIdx.x;
    float s = 0.f;
    #pragma unroll
    for (int h = 0; h < Hh; h++)
        s += kv[((long long)(b*Nkv + h*Ww + w)) * Cq + c];
    out[((long long)(b*Ww + w)) * Cq + c] = s * (1.0f / Hh);
}

// ---------------------------------------------------------------------------
// LayerNorm over C=384 (128 threads, 3 elems/thread)
// ---------------------------------------------------------------------------
__global__ void ln_kernel(const float* __restrict__ x, const float* __restrict__ g,
                          const float* __restrict__ b, float* __restrict__ y)
{
    long long row = blockIdx.x;
    const float* px = x + row * Cq;
    float* py = y + row * Cq;
    float v[3]; float s = 0.f;
    #pragma unroll
    for (int j = 0; j < 3; j++) { v[j] = px[threadIdx.x + j*128]; s += v[j]; }
    float mean = blk_reduce_sum(s) * (1.0f / Cq);
    float sq = 0.f;
    #pragma unroll
    for (int j = 0; j < 3; j++) { float d = v[j] - mean; sq += d*d; }
    float var = blk_reduce_sum(sq) * (1.0f / Cq);
    float rstd = rsqrtf(var + 1e-6f);
    #pragma unroll
    for (int j = 0; j < 3; j++) {
        int c = threadIdx.x + j*128;
        py[c] = (v[j] - mean) * rstd * g[c] + b[c];
    }
}

// ---------------------------------------------------------------------------
// Row softmax (in place), row length L
// ---------------------------------------------------------------------------
__global__ void softmax_kernel(float* __restrict__ x, int L)
{
    long long row = blockIdx.x;
    float* p = x + row * (long long)L;
    float m = -3.4e38f;
    for (int i = threadIdx.x; i < L; i += blockDim.x) m = fmaxf(m, p[i]);
    m = blk_reduce_max(m);
    float s = 0.f;
    for (int i = threadIdx.x; i < L; i += blockDim.x) {
        float e = expf(p[i] - m); p[i] = e; s += e;
    }
    s = blk_reduce_sum(s);
    float inv = 1.0f / s;
    for (int i = threadIdx.x; i < L; i += blockDim.x) p[i] *= inv;
}

// ---------------------------------------------------------------------------
// p_t[row] = sigmoid( sum_c tanh(tbuf[row,c]) * vp_w[c] + vp_b ) * W
// ---------------------------------------------------------------------------
__global__ void pt_kernel(const float* __restrict__ t, const float* __restrict__ vw,
                          const float* __restrict__ vb, float* __restrict__ pt)
{
    long long row = blockIdx.x;
    float s = 0.f;
    for (int c = threadIdx.x; c < Cq; c += blockDim.x)
        s += tanhf(t[row*Cq + c]) * vw[c];
    s = blk_reduce_sum(s);
    if (threadIdx.x == 0)
        pt[row] = (float)Ww / (1.0f + expf(-(s + vb[0])));
}

// ---------------------------------------------------------------------------
// scores[row, w] *= exp(-(w - pt[row])^2 / 18)
// ---------------------------------------------------------------------------
__global__ void gauss_kernel(float* __restrict__ sc, const float* __restrict__ pt)
{
    long long row = blockIdx.x;
    float p = pt[row];
    float w = (float)threadIdx.x;
    float d = w - p;
    sc[row * Ww + threadIdx.x] *= expf(-d*d * (1.0f/18.0f));
}

// ---------------------------------------------------------------------------
// Host launcher
// ---------------------------------------------------------------------------
static void gemm(const float* A, const float* B, const float* bias, float* C,
                 int M, int N, int K, int lda, int ldb, int ldc,
                 long long sAo, long long sAi, long long sBo, long long sBi,
                 long long sCo, long long sCi, int outer, int inner,
                 float alpha, int transB)
{
    dim3 grid(N / 64, M / 64, outer * inner);
    sgemm_kernel<<<grid, 256>>>(A, B, bias, C, M, N, K, lda, ldb, ldc,
                                sAo, sAi, sBo, sBi, sCo, sCi, inner, alpha, transB);
}

extern "C" void kernel_launch(void* const* d_in, const int* in_sizes, int n_in,
                              void* d_out, int out_size)
{
    const float* q         = (const float*)d_in[0];
    const float* kv        = (const float*)d_in[1];
    const float* Wq        = (const float*)d_in[2];
    const float* Wkv       = (const float*)d_in[3];
    const float* Wproj     = (const float*)d_in[4];
    const float* bproj     = (const float*)d_in[5];
    const float* Wp_w      = (const float*)d_in[6];
    const float* Wp_b      = (const float*)d_in[7];
    const float* vp_w      = (const float*)d_in[8];
    const float* vp_b      = (const float*)d_in[9];
    const float* Wqpos     = (const float*)d_in[10];
    const float* bqpos     = (const float*)d_in[11];
    const float* Wrctc     = (const float*)d_in[12];
    const float* brctc     = (const float*)d_in[13];
    const float* ca1_Wq    = (const float*)d_in[14];
    const float* ca1_Wkv   = (const float*)d_in[15];
    const float* ca1_Wproj = (const float*)d_in[16];
    const float* ca1_bproj = (const float*)d_in[17];
    const float* ca2_Wq    = (const float*)d_in[18];
    const float* ca2_Wkv   = (const float*)d_in[19];
    const float* ca2_Wproj = (const float*)d_in[20];
    const float* ca2_bproj = (const float*)d_in[21];
    const float* g_q1      = (const float*)d_in[22];
    const float* b_q1      = (const float*)d_in[23];
    const float* g_kv1     = (const float*)d_in[24];
    const float* b_kv1     = (const float*)d_in[25];
    const float* g_q2      = (const float*)d_in[26];
    const float* b_q2      = (const float*)d_in[27];
    const float* g_kv2     = (const float*)d_in[28];
    const float* b_kv2     = (const float*)d_in[29];
    float* out = (float*)d_out;

    float* scr = nullptr;
    cudaGetSymbolAddress((void**)&scr, SCR);

    float* decm   = scr + OFF_DECM;
    float* dec    = scr + OFF_DEC;
    float* lndec  = scr + OFF_LNDEC;
    float* kvmain = scr + OFF_KVMAIN;
    float* kv2    = scr + OFF_KV2;
    float* kv1    = scr + OFF_KV1;
    float* qh     = scr + OFF_QH;
    float* p0     = scr + OFF_P0;
    float* lnA    = scr + OFF_LNA;
    float* lnB    = scr + OFF_LNB;
    float* qh1    = scr + OFF_QH1;
    float* x1     = scr + OFF_X1;
    float* p1     = scr + OFF_P1;
    float* qh2    = scr + OFF_QH2;
    float* x2     = scr + OFF_X2;
    float* p2     = scr + OFF_P2;
    float* tbuf   = scr + OFF_TBUF;
    float* xmain  = scr + OFF_XMAIN;
    float* sc1    = scr + OFF_SC1;
    float* sc2    = scr + OFF_SC2;
    float* scm    = scr + OFF_SCM;
    float* pt     = scr + OFF_PT;

    const float scale_main = rsqrtf((float)Cq);   // hd = 384 for nh=1
    const float scale_h    = rsqrtf((float)HD2);  // hd = 192 for nh=2

    // 1. dec mean over H
    mean_h_kernel<<<Bq*Ww, Cq>>>(kv, decm);

    // 2. dec = decm @ Wrctc + brctc      [B, 512, 384]
    gemm(decm, Wrctc, brctc, dec, Ww, Cq, Cq, Cq, Cq, Cq,
         (long long)Ww*Cq, 0, 0, 0, (long long)Ww*Cq, 0, Bq, 1, 1.0f, 0);

    // 3. qh = (q @ Wq) * scale_main     [B, 128, 384]
    gemm(q, Wq, nullptr, qh, Sq, Cq, Cq, Cq, Cq, Cq,
         (long long)Sq*Cq, 0, 0, 0, (long long)Sq*Cq, 0, Bq, 1, scale_main, 0);

    // 4. kvmain = dec @ Wkv             [B, 512, 768]
    gemm(dec, Wkv, nullptr, kvmain, Ww, 2*Cq, Cq, Cq, 2*Cq, 2*Cq,
         (long long)Ww*Cq, 0, 0, 0, (long long)Ww*2*Cq, 0, Bq, 1, 1.0f, 0);

    // 5. p0 = q @ Wqpos + bqpos
    gemm(q, Wqpos, bqpos, p0, Sq, Cq, Cq, Cq, Cq, Cq,
         (long long)Sq*Cq, 0, 0, 0, (long long)Sq*Cq, 0, Bq, 1, 1.0f, 0);

    // 6/7. LayerNorms for ca1
    ln_kernel<<<Bq*Sq, 128>>>(p0, g_q1, b_q1, lnA);
    ln_kernel<<<Bq*Sq, 128>>>(q,  g_kv1, b_kv1, lnB);

    // 8. qh1 = (lnA @ ca1_Wq) * scale_h
    gemm(lnA, ca1_Wq, nullptr, qh1, Sq, Cq, Cq, Cq, Cq, Cq,
         (long long)Sq*Cq, 0, 0, 0, (long long)Sq*Cq, 0, Bq, 1, scale_h, 0);

    // 9. kv1 = lnB @ ca1_Wkv            [B, 128, 768]
    gemm(lnB, ca1_Wkv, nullptr, kv1, Sq, 2*Cq, Cq, Cq, 2*Cq, 2*Cq,
         (long long)Sq*Cq, 0, 0, 0, (long long)Sq*2*Cq, 0, Bq, 1, 1.0f, 0);

    // 10. sc1[b,h] = qh1_h @ k1_h^T     [B, 2, 128, 128]
    gemm(qh1, kv1, nullptr, sc1, Sq, Sq, HD2, Cq, 2*Cq, Sq,
         (long long)Sq*Cq, HD2, (long long)Sq*2*Cq, HD2,
         (long long)2*Sq*Sq, (long long)Sq*Sq, Bq, 2, 1.0f, 1);

    // 11. softmax over 128 keys
    softmax_kernel<<<Bq*2*Sq, 128>>>(sc1, Sq);

    // 12. x1[b,:,h*192:] = sc1 @ v1_h   [B, 128, 384]
    gemm(sc1, kv1 + Cq, nullptr, x1, Sq, HD2, Sq, Sq, 2*Cq, Cq,
         (long long)2*Sq*Sq, (long long)Sq*Sq, (long long)Sq*2*Cq, HD2,
         (long long)Sq*Cq, HD2, Bq, 2, 1.0f, 0);

    // 13. p1 = x1 @ ca1_Wproj + ca1_bproj
    gemm(x1, ca1_Wproj, ca1_bproj, p1, Sq, Cq, Cq, Cq, Cq, Cq,
         (long long)Sq*Cq, 0, 0, 0, (long long)Sq*Cq, 0, Bq, 1, 1.0f, 0);

    // 14/15. LayerNorms for ca2
    ln_kernel<<<Bq*Sq, 128>>>(p1, g_q2, b_q2, lnA);   // reuse lnA
    ln_kernel<<<Bq*Ww, 128>>>(dec, g_kv2, b_kv2, lndec);

    // 16. qh2 = (lnA @ ca2_Wq) * scale_h
    gemm(lnA, ca2_Wq, nullptr, qh2, Sq, Cq, Cq, Cq, Cq, Cq,
         (long long)Sq*Cq, 0, 0, 0, (long long)Sq*Cq, 0, Bq, 1, scale_h, 0);

    // 17. kv2 = lndec @ ca2_Wkv         [B, 512, 768]
    gemm(lndec, ca2_Wkv, nullptr, kv2, Ww, 2*Cq, Cq, Cq, 2*Cq, 2*Cq,
         (long long)Ww*Cq, 0, 0, 0, (long long)Ww*2*Cq, 0, Bq, 1, 1.0f, 0);

    // 18. sc2[b,h] = qh2_h @ k2_h^T     [B, 2, 128, 512]
    gemm(qh2, kv2, nullptr, sc2, Sq, Ww, HD2, Cq, 2*Cq, Ww,
         (long long)Sq*Cq, HD2, (long long)Ww*2*Cq, HD2,
         (long long)2*Sq*Ww, (long long)Sq*Ww, Bq, 2, 1.0f, 1);

    // 19. softmax over 512 keys
    softmax_kernel<<<Bq*2*Sq, 256>>>(sc2, Ww);

    // 20. x2 = sc2 @ v2_h               [B, 128, 384]
    gemm(sc2, kv2 + Cq, nullptr, x2, Sq, HD2, Ww, Ww, 2*Cq, Cq,
         (long long)2*Sq*Ww, (long long)Sq*Ww, (long long)Ww*2*Cq, HD2,
         (long long)Sq*Cq, HD2, Bq, 2, 1.0f, 0);

    // 21. p2 = x2 @ ca2_Wproj + ca2_bproj
    gemm(x2, ca2_Wproj, ca2_bproj, p2, Sq, Cq, Cq, Cq, Cq, Cq,
         (long long)Sq*Cq, 0, 0, 0, (long long)Sq*Cq, 0, Bq, 1, 1.0f, 0);

    // 22. tbuf = p2 @ Wp_w + Wp_b
    gemm(p2, Wp_w, Wp_b, tbuf, Sq, Cq, Cq, Cq, Cq, Cq,
         (long long)Sq*Cq, 0, 0, 0, (long long)Sq*Cq, 0, Bq, 1, 1.0f, 0);

    // 23. p_t
    pt_kernel<<<Bq*Sq, 128>>>(tbuf, vp_w, vp_b, pt);

    // 24. main scores = qh @ k_main^T   [B, 128, 512]
    gemm(qh, kvmain, nullptr, scm, Sq, Ww, Cq, Cq, 2*Cq, Ww,
         (long long)Sq*Cq, 0, (long long)Ww*2*Cq, 0,
         (long long)Sq*Ww, 0, Bq, 1, 1.0f, 1);

    // 25. gaussian window multiply
    gauss_kernel<<<Bq*Sq, Ww>>>(scm, pt);

    // 26. softmax over W
    softmax_kernel<<<Bq*Sq, 256>>>(scm, Ww);

    // 27. xmain = scm @ v_main          [B, 128, 384]
    gemm(scm, kvmain + Cq, nullptr, xmain, Sq, Cq, Ww, Ww, 2*Cq, Cq,
         (long long)Sq*Ww, 0, (long long)Ww*2*Cq, 0,
         (long long)Sq*Cq, 0, Bq, 1, 1.0f, 0);

    // 28. out = xmain @ Wproj + bproj
    gemm(xmain, Wproj, bproj, out, Sq, Cq, Cq, Cq, Cq, Cq,
         (long long)Sq*Cq, 0, 0, 0, (long long)Sq*Cq, 0, Bq, 1, 1.0f, 0);
}

// round 4
// speedup vs baseline: 1.4941x; 1.4941x over previous
#include <cuda_runtime.h>
#include <cuda_bf16.h>
#include <math.h>
#include <stdint.h>

// Problem constants (fixed by setup_inputs)
#define Bq   32
#define Sq   128
#define Cq   384
#define Hh   8
#define Ww   512
#define Nkv  (Hh*Ww)        // 4096
#define HD2  192            // head dim for nh=2 cross-attn
// SIGMA = 3 -> 2*sigma^2 = 18

// ---------------------------------------------------------------------------
// Scratch (single __device__ global; no allocations allowed)
// ---------------------------------------------------------------------------
#define SZ_BWC   (Bq*Ww*Cq)
#define SZ_BW2C  (Bq*Ww*2*Cq)
#define SZ_BSC   (Bq*Sq*Cq)
#define SZ_BS2C  (Bq*Sq*2*Cq)
#define SZ_SC1   (Bq*2*Sq*Sq)
#define SZ_SC2   (Bq*2*Sq*Ww)
#define SZ_SCM   (Bq*Sq*Ww)
#define SZ_PT    (Bq*Sq)

#define OFF_DECM   0
#define OFF_DEC    (OFF_DECM + SZ_BWC)
#define OFF_LNDEC  (OFF_DEC + SZ_BWC)
#define OFF_KVMAIN (OFF_LNDEC + SZ_BWC)
#define OFF_KV2    (OFF_KVMAIN + SZ_BW2C)
#define OFF_KV1    (OFF_KV2 + SZ_BW2C)
#define OFF_QH     (OFF_KV1 + SZ_BS2C)
#define OFF_P0     (OFF_QH   + SZ_BSC)
#define OFF_LNA    (OFF_P0   + SZ_BSC)
#define OFF_LNB    (OFF_LNA  + SZ_BSC)
#define OFF_QH1    (OFF_LNB  + SZ_BSC)
#define OFF_X1     (OFF_QH1  + SZ_BSC)
#define OFF_P1     (OFF_X1   + SZ_BSC)
#define OFF_QH2    (OFF_P1   + SZ_BSC)
#define OFF_X2     (OFF_QH2  + SZ_BSC)
#define OFF_P2     (OFF_X2   + SZ_BSC)
#define OFF_TBUF   (OFF_P2   + SZ_BSC)
#define OFF_XMAIN  (OFF_TBUF + SZ_BSC)
#define OFF_SC1    (OFF_XMAIN+ SZ_BSC)
#define OFF_SC2    (OFF_SC1  + SZ_SC1)
#define OFF_SCM    (OFF_SC2  + SZ_SC2)
#define OFF_PT     (OFF_SCM  + SZ_SCM)
#define SCR_TOTAL  (OFF_PT + SZ_PT)

__device__ float SCR[SCR_TOTAL];

// ---------------------------------------------------------------------------
// Block reductions
// ---------------------------------------------------------------------------
__device__ __forceinline__ float blk_reduce_sum(float v) {
    __shared__ float sh[32];
    int lane = threadIdx.x & 31, w = threadIdx.x >> 5;
    #pragma unroll
    for (int o = 16; o; o >>= 1) v += __shfl_xor_sync(0xffffffffu, v, o);
    __syncthreads();
    if (lane == 0) sh[w] = v;
    __syncthreads();
    int nw = (blockDim.x + 31) >> 5;
    float r = (lane < nw) ? sh[lane] : 0.f;
    #pragma unroll
    for (int o = 16; o; o >>= 1) r += __shfl_xor_sync(0xffffffffu, r, o);
    return r;
}

__device__ __forceinline__ float blk_reduce_max(float v) {
    __shared__ float sh[32];
    int lane = threadIdx.x & 31, w = threadIdx.x >> 5;
    #pragma unroll
    for (int o = 16; o; o >>= 1) v = fmaxf(v, __shfl_xor_sync(0xffffffffu, v, o));
    __syncthreads();
    if (lane == 0) sh[w] = v;
    __syncthreads();
    int nw = (blockDim.x + 31) >> 5;
    float r = (lane < nw) ? sh[lane] : -3.4e38f;
    #pragma unroll
    for (int o = 16; o; o >>= 1) r = fmaxf(r, __shfl_xor_sync(0xffffffffu, r, o));
    return r;
}

// ---------------------------------------------------------------------------
// Packed f32x2 FMA (sm_103a). Accumulator/operands are 64-bit packed pairs.
// ---------------------------------------------------------------------------
#define FMA2(c, a, b) \
    asm("fma.rn.f32x2 %0, %1, %2, %0;" : "+l"(c) : "l"(a), "l"(b))

// ---------------------------------------------------------------------------
// SGEMM v2: C = alpha * A @ op(B) (+ bias)
//   Block tile BM x 64, K-tile 16. Per-thread micro-tile 8(M) x 4(N),
//   accumulated as 4 M-pairs x 4 N in packed f32x2 registers.
//   THREADS = BM*64/32. Requirements: M%BM==0, N%64==0, K%16==0,
//   leading dims multiple of 4.
// ---------------------------------------------------------------------------
template<int BM, int THREADS>
__global__ __launch_bounds__(THREADS)
void sgemm2_kernel(const float* __restrict__ A, const float* __restrict__ B,
                   const float* __restrict__ bias, float* __restrict__ C,
                   int M, int N, int K, int lda, int ldb, int ldc,
                   long long sAo, long long sAi,
                   long long sBo, long long sBi,
                   long long sCo, long long sCi,
                   int inner, float alpha, int transB)
{
    constexpr int BN = 64;
    constexpr int LAS = BM + 4;   // row stride keeps 16B alignment (multiple of 4)
    constexpr int LBS = BN + 4;
    __shared__ float As[16][LAS];
    __shared__ float Bs[16][LBS];

    int z = blockIdx.z;
    int o = z / inner, ii = z - o * inner;
    A += (long long)o * sAo + (long long)ii * sAi;
    B += (long long)o * sBo + (long long)ii * sBi;
    C += (long long)o * sCo + (long long)ii * sCi;

    const int tid = threadIdx.x;
    const int tx = tid & 15;          // N direction (4 cols each)
    const int ty = tid >> 4;          // M direction (8 rows each)
    const int row0 = blockIdx.y * BM;
    const int col0 = blockIdx.x * BN;

    // A global-load mapping: 2 threads per row, 8 consecutive k each
    const int am = tid >> 1;
    const int ak = (tid & 1) << 3;

    float4 pa0, pa1, pb0, pb1;

    // ---- initial prefetch (kk = 0) ----
    {
        const float* pA = &A[(long long)(row0 + am) * lda + ak];
        pa0 = *(const float4*)pA;
        pa1 = *(const float4*)(pA + 4);
    }
    if (!transB) {
        if (THREADS == 256) {
            int k = tid >> 4, n4 = (tid & 15) << 2;
            pb0 = *(const float4*)&B[(long long)k * ldb + col0 + n4];
        } else {
            int k = tid >> 3, n8 = (tid & 7) << 3;
            const float* pB = &B[(long long)k * ldb + col0 + n8];
            pb0 = *(const float4*)pB;
            pb1 = *(const float4*)(pB + 4);
        }
    } else {
        if (THREADS == 256) {
            int n = tid >> 2, k4 = (tid & 3) << 2;
            pb0 = *(const float4*)&B[(long long)(col0 + n) * ldb + k4];
        } else {
            int n = tid >> 1, k8 = (tid & 1) << 3;
            const float* pB = &B[(long long)(col0 + n) * ldb + k8];
            pb0 = *(const float4*)pB;
            pb1 = *(const float4*)(pB + 4);
        }
    }

    uint64_t acc[4][4];
    #pragma unroll
    for (int i = 0; i < 4; i++)
        #pragma unroll
        for (int j = 0; j < 4; j++) acc[i][j] = 0ull;

    for (int kk = 0; kk < K; kk += 16) {
        __syncthreads();
        // ---- store prefetched tiles to smem ----
        As[ak+0][am] = pa0.x; As[ak+1][am] = pa0.y;
        As[ak+2][am] = pa0.z; As[ak+3][am] = pa0.w;
        As[ak+4][am] = pa1.x; As[ak+5][am] = pa1.y;
        As[ak+6][am] = pa1.z; As[ak+7][am] = pa1.w;

        if (!transB) {
            if (THREADS == 256) {
                int k = tid >> 4, n4 = (tid & 15) << 2;
                *(float4*)&Bs[k][n4] = pb0;
            } else {
                int k = tid >> 3, n8 = (tid & 7) << 3;
                *(float4*)&Bs[k][n8]     = pb0;
                *(float4*)&Bs[k][n8 + 4] = pb1;
            }
        } else {
            if (THREADS == 256) {
                int n = tid >> 2, k4 = (tid & 3) << 2;
                Bs[k4+0][n] = pb0.x; Bs[k4+1][n] = pb0.y;
                Bs[k4+2][n] = pb0.z; Bs[k4+3][n] = pb0.w;
            } else {
                int n = tid >> 1, k8 = (tid & 1) << 3;
                Bs[k8+0][n] = pb0.x; Bs[k8+1][n] = pb0.y;
                Bs[k8+2][n] = pb0.z; Bs[k8+3][n] = pb0.w;
                Bs[k8+4][n] = pb1.x; Bs[k8+5][n] = pb1.y;
                Bs[k8+6][n] = pb1.z; Bs[k8+7][n] = pb1.w;
            }
        }
        __syncthreads();

        // ---- prefetch next tile (overlaps with compute below) ----
        if (kk + 16 < K) {
            const float* pA = &A[(long long)(row0 + am) * lda + kk + 16 + ak];
            pa0 = *(const float4*)pA;
            pa1 = *(const float4*)(pA + 4);
            if (!transB) {
                if (THREADS == 256) {
                    int k = tid >> 4, n4 = (tid & 15) << 2;
                    pb0 = *(const float4*)&B[(long long)(kk + 16 + k) * ldb + col0 + n4];
                } else {
                    int k = tid >> 3, n8 = (tid & 7) << 3;
                    const float* pB = &B[(long long)(kk + 16 + k) * ldb + col0 + n8];
                    pb0 = *(const float4*)pB;
                    pb1 = *(const float4*)(pB + 4);
                }
            } else {
                if (THREADS == 256) {
                    int n = tid >> 2, k4 = (tid & 3) << 2;
                    pb0 = *(const float4*)&B[(long long)(col0 + n) * ldb + kk + 16 + k4];
                } else {
                    int n = tid >> 1, k8 = (tid & 1) << 3;
                    const float* pB = &B[(long long)(col0 + n) * ldb + kk + 16 + k8];
                    pb0 = *(const float4*)pB;
                    pb1 = *(const float4*)(pB + 4);
                }
            }
        }

        // ---- compute ----
        #pragma unroll
        for (int k = 0; k < 16; k++) {
            const double2* Ap = (const double2*)&As[k][ty << 3];
            double2 d0 = Ap[0];
            double2 d1 = Ap[1];
            uint64_t a0 = __double_as_longlong(d0.x);
            uint64_t a1 = __double_as_longlong(d0.y);
            uint64_t a2 = __double_as_longlong(d1.x);
            uint64_t a3 = __double_as_longlong(d1.y);
            float4 bv = *(const float4*)&Bs[k][tx << 2];
            uint64_t b0, b1, b2, b3;
            asm("mov.b64 %0, {%1, %1};" : "=l"(b0) : "f"(bv.x));
            asm("mov.b64 %0, {%1, %1};" : "=l"(b1) : "f"(bv.y));
            asm("mov.b64 %0, {%1, %1};" : "=l"(b2) : "f"(bv.z));
            asm("mov.b64 %0, {%1, %1};" : "=l"(b3) : "f"(bv.w));
            FMA2(acc[0][0], a0, b0); FMA2(acc[0][1], a0, b1);
            FMA2(acc[0][2], a0, b2); FMA2(acc[0][3], a0, b3);
            FMA2(acc[1][0], a1, b0); FMA2(acc[1][1], a1, b1);
            FMA2(acc[1][2], a1, b2); FMA2(acc[1][3], a1, b3);
            FMA2(acc[2][0], a2, b0); FMA2(acc[2][1], a2, b1);
            FMA2(acc[2][2], a2, b2); FMA2(acc[2][3], a2, b3);
            FMA2(acc[3][0], a3, b0); FMA2(acc[3][1], a3, b1);
            FMA2(acc[3][2], a3, b2); FMA2(acc[3][3], a3, b3);
        }
    }

    // ---- epilogue ----
    const int c0 = col0 + (tx << 2);
    float4 bb = make_float4(0.f, 0.f, 0.f, 0.f);
    if (bias) bb = *(const float4*)&bias[c0];
    #pragma unroll
    for (int mp = 0; mp < 4; mp++) {
        int r = row0 + (ty << 3) + (mp << 1);
        float lo[4], hi[4];
        #pragma unroll
        for (int n = 0; n < 4; n++) {
            asm("mov.b64 {%0, %1}, %2;" : "=f"(lo[n]), "=f"(hi[n]) : "l"(acc[mp][n]));
            lo[n] = lo[n] * alpha;
            hi[n] = hi[n] * alpha;
        }
        lo[0] += bb.x; lo[1] += bb.y; lo[2] += bb.z; lo[3] += bb.w;
        hi[0] += bb.x; hi[1] += bb.y; hi[2] += bb.z; hi[3] += bb.w;
        *(float4*)&C[(long long)r * ldc + c0]       = make_float4(lo[0], lo[1], lo[2], lo[3]);
        *(float4*)&C[(long long)(r + 1) * ldc + c0] = make_float4(hi[0], hi[1], hi[2], hi[3]);
    }
}

// ---------------------------------------------------------------------------
// dec mean over H:  decm[b,w,c] = mean_h kv[b, h*W + w, c]
// ---------------------------------------------------------------------------
__global__ void mean_h_kernel(const float* __restrict__ kv, float* __restrict__ out)
{
    int bw = blockIdx.x;
    int b = bw >> 9;
    int w = bw & 511;
    int c = threadIdx.x;
    float s = 0.f;
    #pragma unroll
    for (int h = 0; h < Hh; h++)
        s += kv[((long long)(b*Nkv + h*Ww + w)) * Cq + c];
    out[((long long)(b*Ww + w)) * Cq + c] = s * (1.0f / Hh);
}

// ---------------------------------------------------------------------------
// LayerNorm over C=384 (128 threads, 3 elems/thread)
// ---------------------------------------------------------------------------
__global__ void ln_kernel(const float* __restrict__ x, const float* __restrict__ g,
                          const float* __restrict__ b, float* __restrict__ y)
{
    long long row = blockIdx.x;
    const float* px = x + row * Cq;
    float* py = y + row * Cq;
    float v[3]; float s = 0.f;
    #pragma unroll
    for (int j = 0; j < 3; j++) { v[j] = px[threadIdx.x + j*128]; s += v[j]; }
    float mean = blk_reduce_sum(s) * (1.0f / Cq);
    float sq = 0.f;
    #pragma unroll
    for (int j = 0; j < 3; j++) { float d = v[j] - mean; sq += d*d; }
    float var = blk_reduce_sum(sq) * (1.0f / Cq);
    float rstd = rsqrtf(var + 1e-6f);
    #pragma unroll
    for (int j = 0; j < 3; j++) {
        int c = threadIdx.x + j*128;
        py[c] = (v[j] - mean) * rstd * g[c] + b[c];
    }
}

// ---------------------------------------------------------------------------
// Row softmax (in place), row length L
// ---------------------------------------------------------------------------
__global__ void softmax_kernel(float* __restrict__ x, int L)
{
    long long row = blockIdx.x;
    float* p = x + row * (long long)L;
    float m = -3.4e38f;
    for (int i = threadIdx.x; i < L; i += blockDim.x) m = fmaxf(m, p[i]);
    m = blk_reduce_max(m);
    float s = 0.f;
    for (int i = threadIdx.x; i < L; i += blockDim.x) {
        float e = expf(p[i] - m); p[i] = e; s += e;
    }
    s = blk_reduce_sum(s);
    float inv = 1.0f / s;
    for (int i = threadIdx.x; i < L; i += blockDim.x) p[i] *= inv;
}

// ---------------------------------------------------------------------------
// p_t[row] = sigmoid( sum_c tanh(tbuf[row,c]) * vp_w[c] + vp_b ) * W
// ---------------------------------------------------------------------------
__global__ void pt_kernel(const float* __restrict__ t, const float* __restrict__ vw,
                          const float* __restrict__ vb, float* __restrict__ pt)
{
    long long row = blockIdx.x;
    float s = 0.f;
    for (int c = threadIdx.x; c < Cq; c += blockDim.x)
        s += tanhf(t[row*Cq + c]) * vw[c];
    s = blk_reduce_sum(s);
    if (threadIdx.x == 0)
        pt[row] = (float)Ww / (1.0f + expf(-(s + vb[0])));
}

// ---------------------------------------------------------------------------
// scores[row, w] *= exp(-(w - pt[row])^2 / 18)
// ---------------------------------------------------------------------------
__global__ void gauss_kernel(float* __restrict__ sc, const float* __restrict__ pt)
{
    long long row = blockIdx.x;
    float p = pt[row];
    float w = (float)threadIdx.x;
    float d = w - p;
    sc[row * Ww + threadIdx.x] *= expf(-d*d * (1.0f/18.0f));
}

// ---------------------------------------------------------------------------
// Host launcher
// ---------------------------------------------------------------------------
static void gemm(const float* A, const float* B, const float* bias, float* C,
                 int M, int N, int K, int lda, int ldb, int ldc,
                 long long sAo, long long sAi, long long sBo, long long sBi,
                 long long sCo, long long sCi, int outer, int inner,
                 float alpha, int transB)
{
    int batches = outer * inner;
    if (M % 128 == 0 && M > 128) {
        dim3 grid(N / 64, M / 128, batches);
        sgemm2_kernel<128, 256><<<grid, 256>>>(A, B, bias, C, M, N, K, lda, ldb, ldc,
                                               sAo, sAi, sBo, sBi, sCo, sCi,
                                               inner, alpha, transB);
    } else {
        dim3 grid(N / 64, M / 64, batches);
        sgemm2_kernel<64, 128><<<grid, 128>>>(A, B, bias, C, M, N, K, lda, ldb, ldc,
                                              sAo, sAi, sBo, sBi, sCo, sCi,
                                              inner, alpha, transB);
    }
}

extern "C" void kernel_launch(void* const* d_in, const int* in_sizes, int n_in,
                              void* d_out, int out_size)
{
    const float* q         = (const float*)d_in[0];
    const float* kv        = (const float*)d_in[1];
    const float* Wq        = (const float*)d_in[2];
    const float* Wkv       = (const float*)d_in[3];
    const float* Wproj     = (const float*)d_in[4];
    const float* bproj     = (const float*)d_in[5];
    const float* Wp_w      = (const float*)d_in[6];
    const float* Wp_b      = (const float*)d_in[7];
    const float* vp_w      = (const float*)d_in[8];
    const float* vp_b      = (const float*)d_in[9];
    const float* Wqpos     = (const float*)d_in[10];
    const float* bqpos     = (const float*)d_in[11];
    const float* Wrctc     = (const float*)d_in[12];
    const float* brctc     = (const float*)d_in[13];
    const float* ca1_Wq    = (const float*)d_in[14];
    const float* ca1_Wkv   = (const float*)d_in[15];
    const float* ca1_Wproj = (const float*)d_in[16];
    const float* ca1_bproj = (const float*)d_in[17];
    const float* ca2_Wq    = (const float*)d_in[18];
    const float* ca2_Wkv   = (const float*)d_in[19];
    const float* ca2_Wproj = (const float*)d_in[20];
    const float* ca2_bproj = (const float*)d_in[21];
    const float* g_q1      = (const float*)d_in[22];
    const float* b_q1      = (const float*)d_in[23];
    const float* g_kv1     = (const float*)d_in[24];
    const float* b_kv1     = (const float*)d_in[25];
    const float* g_q2      = (const float*)d_in[26];
    const float* b_q2      = (const float*)d_in[27];
    const float* g_kv2     = (const float*)d_in[28];
    const float* b_kv2     = (const float*)d_in[29];
    float* out = (float*)d_out;

    float* scr = nullptr;
    cudaGetSymbolAddress((void**)&scr, SCR);

    float* decm   = scr + OFF_DECM;
    float* dec    = scr + OFF_DEC;
    float* lndec  = scr + OFF_LNDEC;
    float* kvmain = scr + OFF_KVMAIN;
    float* kv2    = scr + OFF_KV2;
    float* kv1    = scr + OFF_KV1;
    float* qh     = scr + OFF_QH;
    float* p0     = scr + OFF_P0;
    float* lnA    = scr + OFF_LNA;
    float* lnB    = scr + OFF_LNB;
    float* qh1    = scr + OFF_QH1;
    float* x1     = scr + OFF_X1;
    float* p1     = scr + OFF_P1;
    float* qh2    = scr + OFF_QH2;
    float* x2     = scr + OFF_X2;
    float* p2     = scr + OFF_P2;
    float* tbuf   = scr + OFF_TBUF;
    float* xmain  = scr + OFF_XMAIN;
    float* sc1    = scr + OFF_SC1;
    float* sc2    = scr + OFF_SC2;
    float* scm    = scr + OFF_SCM;
    float* pt     = scr + OFF_PT;

    const float scale_main = rsqrtf((float)Cq);   // hd = 384 for nh=1
    const float scale_h    = rsqrtf((float)HD2);  // hd = 192 for nh=2

    // 1. dec mean over H
    mean_h_kernel<<<Bq*Ww, Cq>>>(kv, decm);

    // 2. dec = decm @ Wrctc + brctc      [B, 512, 384]
    gemm(decm, Wrctc, brctc, dec, Ww, Cq, Cq, Cq, Cq, Cq,
         (long long)Ww*Cq, 0, 0, 0, (long long)Ww*Cq, 0, Bq, 1, 1.0f, 0);

    // 3. qh = (q @ Wq) * scale_main     [B, 128, 384]
    gemm(q, Wq, nullptr, qh, Sq, Cq, Cq, Cq, Cq, Cq,
         (long long)Sq*Cq, 0, 0, 0, (long long)Sq*Cq, 0, Bq, 1, scale_main, 0);

    // 4. kvmain = dec @ Wkv             [B, 512, 768]
    gemm(dec, Wkv, nullptr, kvmain, Ww, 2*Cq, Cq, Cq, 2*Cq, 2*Cq,
         (long long)Ww*Cq, 0, 0, 0, (long long)Ww*2*Cq, 0, Bq, 1, 1.0f, 0);

    // 5. p0 = q @ Wqpos + bqpos
    gemm(q, Wqpos, bqpos, p0, Sq, Cq, Cq, Cq, Cq, Cq,
         (long long)Sq*Cq, 0, 0, 0, (long long)Sq*Cq, 0, Bq, 1, 1.0f, 0);

    // 6/7. LayerNorms for ca1
    ln_kernel<<<Bq*Sq, 128>>>(p0, g_q1, b_q1, lnA);
    ln_kernel<<<Bq*Sq, 128>>>(q,  g_kv1, b_kv1, lnB);

    // 8. qh1 = (lnA @ ca1_Wq) * scale_h
    gemm(lnA, ca1_Wq, nullptr, qh1, Sq, Cq, Cq, Cq, Cq, Cq,
         (long long)Sq*Cq, 0, 0, 0, (long long)Sq*Cq, 0, Bq, 1, scale_h, 0);

    // 9. kv1 = lnB @ ca1_Wkv            [B, 128, 768]
    gemm(lnB, ca1_Wkv, nullptr, kv1, Sq, 2*Cq, Cq, Cq, 2*Cq, 2*Cq,
         (long long)Sq*Cq, 0, 0, 0, (long long)Sq*2*Cq, 0, Bq, 1, 1.0f, 0);

    // 10. sc1[b,h] = qh1_h @ k1_h^T     [B, 2, 128, 128]
    gemm(qh1, kv1, nullptr, sc1, Sq, Sq, HD2, Cq, 2*Cq, Sq,
         (long long)Sq*Cq, HD2, (long long)Sq*2*Cq, HD2,
         (long long)2*Sq*Sq, (long long)Sq*Sq, Bq, 2, 1.0f, 1);

    // 11. softmax over 128 keys
    softmax_kernel<<<Bq*2*Sq, 128>>>(sc1, Sq);

    // 12. x1[b,:,h*192:] = sc1 @ v1_h   [B, 128, 384]
    gemm(sc1, kv1 + Cq, nullptr, x1, Sq, HD2, Sq, Sq, 2*Cq, Cq,
         (long long)2*Sq*Sq, (long long)Sq*Sq, (long long)Sq*2*Cq, HD2,
         (long long)Sq*Cq, HD2, Bq, 2, 1.0f, 0);

    // 13. p1 = x1 @ ca1_Wproj + ca1_bproj
    gemm(x1, ca1_Wproj, ca1_bproj, p1, Sq, Cq, Cq, Cq, Cq, Cq,
         (long long)Sq*Cq, 0, 0, 0, (long long)Sq*Cq, 0, Bq, 1, 1.0f, 0);

    // 14/15. LayerNorms for ca2
    ln_kernel<<<Bq*Sq, 128>>>(p1, g_q2, b_q2, lnA);   // reuse lnA
    ln_kernel<<<Bq*Ww, 128>>>(dec, g_kv2, b_kv2, lndec);

    // 16. qh2 = (lnA @ ca2_Wq) * scale_h
    gemm(lnA, ca2_Wq, nullptr, qh2, Sq, Cq, Cq, Cq, Cq, Cq,
         (long long)Sq*Cq, 0, 0, 0, (long long)Sq*Cq, 0, Bq, 1, scale_h, 0);

    // 17. kv2 = lndec @ ca2_Wkv         [B, 512, 768]
    gemm(lndec, ca2_Wkv, nullptr, kv2, Ww, 2*Cq, Cq, Cq, 2*Cq, 2*Cq,
         (long long)Ww*Cq, 0, 0, 0, (long long)Ww*2*Cq, 0, Bq, 1, 1.0f, 0);

    // 18. sc2[b,h] = qh2_h @ k2_h^T     [B, 2, 128, 512]
    gemm(qh2, kv2, nullptr, sc2, Sq, Ww, HD2, Cq, 2*Cq, Ww,
         (long long)Sq*Cq, HD2, (long long)Ww*2*Cq, HD2,
         (long long)2*Sq*Ww, (long long)Sq*Ww, Bq, 2, 1.0f, 1);

    // 19. softmax over 512 keys
    softmax_kernel<<<Bq*2*Sq, 256>>>(sc2, Ww);

    // 20. x2 = sc2 @ v2_h               [B, 128, 384]
    gemm(sc2, kv2 + Cq, nullptr, x2, Sq, HD2, Ww, Ww, 2*Cq, Cq,
         (long long)2*Sq*Ww, (long long)Sq*Ww, (long long)Ww*2*Cq, HD2,
         (long long)Sq*Cq, HD2, Bq, 2, 1.0f, 0);

    // 21. p2 = x2 @ ca2_Wproj + ca2_bproj
    gemm(x2, ca2_Wproj, ca2_bproj, p2, Sq, Cq, Cq, Cq, Cq, Cq,
         (long long)Sq*Cq, 0, 0, 0, (long long)Sq*Cq, 0, Bq, 1, 1.0f, 0);

    // 22. tbuf = p2 @ Wp_w + Wp_b
    gemm(p2, Wp_w, Wp_b, tbuf, Sq, Cq, Cq, Cq, Cq, Cq,
         (long long)Sq*Cq, 0, 0, 0, (long long)Sq*Cq, 0, Bq, 1, 1.0f, 0);

    // 23. p_t
    pt_kernel<<<Bq*Sq, 128>>>(tbuf, vp_w, vp_b, pt);

    // 24. main scores = qh @ k_main^T   [B, 128, 512]
    gemm(qh, kvmain, nullptr, scm, Sq, Ww, Cq, Cq, 2*Cq, Ww,
         (long long)Sq*Cq, 0, (long long)Ww*2*Cq, 0,
         (long long)Sq*Ww, 0, Bq, 1, 1.0f, 1);

    // 25. gaussian window multiply
    gauss_kernel<<<Bq*Sq, Ww>>>(scm, pt);

    // 26. softmax over W
    softmax_kernel<<<Bq*Sq, 256>>>(scm, Ww);

    // 27. xmain = scm @ v_main          [B, 128, 384]
    gemm(scm, kvmain + Cq, nullptr, xmain, Sq, Cq, Ww, Ww, 2*Cq, Cq,
         (long long)Sq*Ww, 0, (long long)Ww*2*Cq, 0,
         (long long)Sq*Cq, 0, Bq, 1, 1.0f, 0);

    // 28. out = xmain @ Wproj + bproj
    gemm(xmain, Wproj, bproj, out, Sq, Cq, Cq, Cq, Cq, Cq,
         (long long)Sq*Cq, 0, 0, 0, (long long)Sq*Cq, 0, Bq, 1, 1.0f, 0);
}